// round 15
// baseline (speedup 1.0000x reference)
#include <cuda_runtime.h>
#include <cuda_bf16.h>
#include <cstdint>

// Problem dims (fixed by the dataset)
#define NROWS 16384
#define FDIM  1024
#define HDIM  256

#define SMEM_SWIZZLE(off) ((off) ^ (((off) >> 3) & 0x70))

// 3 pipeline stages x (A 16KB | B 16KB) = 98304 B dynamic smem
#define STAGE_BYTES 32768
#define SM_DYN (3 * STAGE_BYTES)

// wdist dynamic smem: buf float[8192] + PS float[8193]
#define WD_SMEM (32768 + 32772)

// ============================================================================
// Device scratch (static allocation is the allowed path)
// ============================================================================
__device__ __nv_bfloat16 X16_buf[NROWS * FDIM];    // 32 MB
__device__ __nv_bfloat16 WeT16_buf[HDIM * FDIM];   // [256][1024]: WeT[n][k] = We[k][n]
__device__ __nv_bfloat16 WdT16_buf[FDIM * HDIM];   // [1024][256]: WdT[n][k] = Wd[k][n]
__device__ __nv_bfloat16 g16_buf[NROWS * HDIM];    // 8 MB
__device__ float  c_buf[NROWS];                    // critic scores (bc dropped: cancels)
__device__ int    np_g;
__device__ double pair_sum_g;
__device__ float  mse_partials[1024];

// ============================================================================
// mma.sync / cp.async helpers (legal on base sm_103 target)
// ============================================================================
__device__ __forceinline__ void ldmatrix_x4(uint32_t& r0, uint32_t& r1,
                                            uint32_t& r2, uint32_t& r3,
                                            uint32_t smem_addr) {
    asm volatile("ldmatrix.sync.aligned.m8n8.x4.shared.b16 {%0,%1,%2,%3}, [%4];"
                 : "=r"(r0), "=r"(r1), "=r"(r2), "=r"(r3) : "r"(smem_addr));
}
__device__ __forceinline__ void mma_16816(float& c0, float& c1, float& c2, float& c3,
                                          uint32_t a0, uint32_t a1, uint32_t a2, uint32_t a3,
                                          uint32_t b0, uint32_t b1) {
    asm volatile("mma.sync.aligned.m16n8k16.row.col.f32.bf16.bf16.f32 "
                 "{%0,%1,%2,%3}, {%4,%5,%6,%7}, {%8,%9}, {%0,%1,%2,%3};"
                 : "+f"(c0), "+f"(c1), "+f"(c2), "+f"(c3)
                 : "r"(a0), "r"(a1), "r"(a2), "r"(a3), "r"(b0), "r"(b1));
}
__device__ __forceinline__ uint32_t smem_u32_of(const void* p) {
    uint32_t a;
    asm("{ .reg .u64 t; cvta.to.shared.u64 t, %1; cvt.u32.u64 %0, t; }" : "=r"(a) : "l"(p));
    return a;
}
__device__ __forceinline__ void cp_async16(uint32_t dst_smem, const void* src) {
    asm volatile("cp.async.cg.shared.global [%0], [%1], 16;"
                 :: "r"(dst_smem), "l"(src));
}
#define CP_COMMIT()  asm volatile("cp.async.commit_group;" ::: "memory")
#define CP_WAIT_1()  asm volatile("cp.async.wait_group 1;" ::: "memory")
#define CP_WAIT_0()  asm volatile("cp.async.wait_group 0;" ::: "memory")

// ============================================================================
// Combined conversion kernel
// ============================================================================
#define XBLOCKS (NROWS * FDIM / 4 / 256)          // 16384
__global__ void __launch_bounds__(256) conv_all_kernel(
    const float* __restrict__ X, const float* __restrict__ We,
    const float* __restrict__ Wd)
{
    if (blockIdx.x < XBLOCKS) {
        int idx = blockIdx.x * 256 + threadIdx.x;
        float4 v = ((const float4*)X)[idx];
        __nv_bfloat162 h0 = __floats2bfloat162_rn(v.x, v.y);
        __nv_bfloat162 h1 = __floats2bfloat162_rn(v.z, v.w);
        uint2 o;
        o.x = *reinterpret_cast<uint32_t*>(&h0);
        o.y = *reinterpret_cast<uint32_t*>(&h1);
        ((uint2*)X16_buf)[idx] = o;
    } else {
        int idx = (blockIdx.x - XBLOCKS) * 256 + threadIdx.x;   // [0, 524288)
        if (idx < NROWS) c_buf[idx] = 0.f;
        if (idx < HDIM * FDIM) {
            int n = idx >> 10, k = idx & 1023;
            WeT16_buf[idx] = __float2bfloat16_rn(We[(size_t)k * HDIM + n]);
        } else {
            int j = idx - HDIM * FDIM;
            int n = j >> 8, k = j & 255;
            WdT16_buf[j] = __float2bfloat16_rn(Wd[(size_t)k * FDIM + n]);
        }
    }
}

// ============================================================================
// Warp-tile MMA over one staged (A,B) 128x64 slab pair.
// ============================================================================
struct MmaCtx { int wm, wn, lane; };

__device__ __forceinline__ void mma_block_iter(
    const MmaCtx& ctx, uint32_t sA, uint32_t sB, float acc[2][8][4])
{
    const int lrow  = ctx.lane & 15;
    const int lcolb = (ctx.lane >> 4) * 16;
    #pragma unroll
    for (int ks = 0; ks < 4; ks++) {
        const int kb = ks * 32;
        uint32_t a[2][4], b[4][4];
        #pragma unroll
        for (int mf = 0; mf < 2; mf++) {
            int off = (ctx.wm * 32 + mf * 16 + lrow) * 128 + kb + lcolb;
            ldmatrix_x4(a[mf][0], a[mf][1], a[mf][2], a[mf][3],
                        sA + SMEM_SWIZZLE(off));
        }
        #pragma unroll
        for (int nf = 0; nf < 4; nf++) {
            int off = (ctx.wn * 64 + nf * 16 + lrow) * 128 + kb + lcolb;
            ldmatrix_x4(b[nf][0], b[nf][1], b[nf][2], b[nf][3],
                        sB + SMEM_SWIZZLE(off));
        }
        #pragma unroll
        for (int mf = 0; mf < 2; mf++)
            #pragma unroll
            for (int nf = 0; nf < 4; nf++) {
                mma_16816(acc[mf][2*nf][0], acc[mf][2*nf][1],
                          acc[mf][2*nf][2], acc[mf][2*nf][3],
                          a[mf][0], a[mf][1], a[mf][2], a[mf][3],
                          b[nf][0], b[nf][2]);
                mma_16816(acc[mf][2*nf+1][0], acc[mf][2*nf+1][1],
                          acc[mf][2*nf+1][2], acc[mf][2*nf+1][3],
                          a[mf][0], a[mf][1], a[mf][2], a[mf][3],
                          b[nf][1], b[nf][3]);
            }
    }
}

__device__ __forceinline__ void stage_tile_async(
    uint32_t dst_u32, const __nv_bfloat16* __restrict__ src,
    int K_TOT, int k0, int tid)
{
    #pragma unroll
    for (int it = 0; it < 4; it++) {
        int idx = tid + it * 256;
        int row = idx >> 3, k8 = idx & 7;
        const void* gp = (const char*)src + ((size_t)row * K_TOT + k0) * 2 + k8 * 16;
        cp_async16(dst_u32 + SMEM_SWIZZLE(row * 128 + k8 * 16), gp);
    }
}

// 3-stage pipelined mainloop with wait_group(1).
__device__ __forceinline__ void gemm_mainloop(
    const MmaCtx& ctx, uint32_t smem_u32,
    const __nv_bfloat16* __restrict__ Ag, const __nv_bfloat16* __restrict__ Bg,
    int K_TOT, int tid, float acc[2][8][4])
{
    const int NS = K_TOT >> 6;
    stage_tile_async(smem_u32,         Ag, K_TOT, 0, tid);
    stage_tile_async(smem_u32 + 16384, Bg, K_TOT, 0, tid);
    CP_COMMIT();
    if (NS > 1) {
        stage_tile_async(smem_u32 + STAGE_BYTES,         Ag, K_TOT, 64, tid);
        stage_tile_async(smem_u32 + STAGE_BYTES + 16384, Bg, K_TOT, 64, tid);
        CP_COMMIT();
    }
    int bufIdx = 0;
    for (int s = 0; s < NS; s++) {
        if (s + 1 < NS) CP_WAIT_1(); else CP_WAIT_0();
        __syncthreads();
        if (s + 2 < NS) {
            int nbi = bufIdx + 2; if (nbi >= 3) nbi -= 3;
            const uint32_t nxt = smem_u32 + nbi * STAGE_BYTES;
            stage_tile_async(nxt,         Ag, K_TOT, (s + 2) << 6, tid);
            stage_tile_async(nxt + 16384, Bg, K_TOT, (s + 2) << 6, tid);
            CP_COMMIT();
        }
        const uint32_t cur = smem_u32 + bufIdx * STAGE_BYTES;
        mma_block_iter(ctx, cur, cur + 16384, acc);
        if (++bufIdx == 3) bufIdx = 0;
    }
}

// ============================================================================
// GEMM1 + fused critic
// ============================================================================
__global__ void __launch_bounds__(256) gemm1_mma_kernel(
    const float* __restrict__ be, const float* __restrict__ Wc)
{
    extern __shared__ __align__(1024) char smem[];
    __shared__ float bias_s[128], Wc_s[128];
    __shared__ float csm[2][128];

    const int tid = threadIdx.x;
    const int warp = tid >> 5;
    const int rowBase = blockIdx.y * 128;
    const int colBase = blockIdx.x * 128;
    if (tid < 128) { bias_s[tid] = be[colBase + tid]; Wc_s[tid] = Wc[colBase + tid]; }

    MmaCtx ctx; ctx.wm = warp & 3; ctx.wn = warp >> 2; ctx.lane = tid & 31;
    uint32_t smem_u32 = smem_u32_of(smem);

    float acc[2][8][4] = {};
    gemm_mainloop(ctx, smem_u32,
                  X16_buf + (size_t)rowBase * FDIM,
                  WeT16_buf + (size_t)colBase * FDIM, FDIM, tid, acc);

    const int g = ctx.lane >> 2, q = ctx.lane & 3;
    float sdot[2][2] = {};
    #pragma unroll
    for (int mf = 0; mf < 2; mf++) {
        #pragma unroll
        for (int nf = 0; nf < 8; nf++) {
            int lcol = ctx.wn * 64 + nf * 8 + q * 2;
            int col  = colBase + lcol;
            float b0 = bias_s[lcol], b1 = bias_s[lcol + 1];
            float w0 = Wc_s[lcol],   w1 = Wc_s[lcol + 1];
            float a0 = acc[mf][nf][0] + b0, a1 = acc[mf][nf][1] + b1;
            float a2 = acc[mf][nf][2] + b0, a3 = acc[mf][nf][3] + b1;
            int row0 = rowBase + ctx.wm * 32 + mf * 16 + g;
            __nv_bfloat162 h0 = __floats2bfloat162_rn(a0, a1);
            __nv_bfloat162 h1 = __floats2bfloat162_rn(a2, a3);
            *(__nv_bfloat162*)(g16_buf + (size_t)row0 * HDIM + col) = h0;
            *(__nv_bfloat162*)(g16_buf + (size_t)(row0 + 8) * HDIM + col) = h1;
            sdot[mf][0] = fmaf(a0, w0, fmaf(a1, w1, sdot[mf][0]));
            sdot[mf][1] = fmaf(a2, w0, fmaf(a3, w1, sdot[mf][1]));
        }
    }
    #pragma unroll
    for (int off = 1; off <= 2; off <<= 1) {
        #pragma unroll
        for (int mf = 0; mf < 2; mf++) {
            sdot[mf][0] += __shfl_xor_sync(0xFFFFFFFFu, sdot[mf][0], off);
            sdot[mf][1] += __shfl_xor_sync(0xFFFFFFFFu, sdot[mf][1], off);
        }
    }
    if (q == 0) {
        #pragma unroll
        for (int mf = 0; mf < 2; mf++) {
            int lr = ctx.wm * 32 + mf * 16 + g;
            csm[ctx.wn][lr]     = sdot[mf][0];
            csm[ctx.wn][lr + 8] = sdot[mf][1];
        }
    }
    __syncthreads();
    if (tid < 128)
        atomicAdd(&c_buf[rowBase + tid], csm[0][tid] + csm[1][tid]);
}

// ============================================================================
// GEMM2 fused MSE
// ============================================================================
__global__ void __launch_bounds__(256) gemm2_mma_kernel(const float* __restrict__ bd)
{
    extern __shared__ __align__(1024) char smem[];
    __shared__ float bias_s[128];
    __shared__ float red[256];

    const int tid = threadIdx.x;
    const int warp = tid >> 5;
    const int rowBase = blockIdx.y * 128;
    const int colBase = blockIdx.x * 128;
    if (tid < 128) bias_s[tid] = bd[colBase + tid];

    MmaCtx ctx; ctx.wm = warp & 3; ctx.wn = warp >> 2; ctx.lane = tid & 31;
    uint32_t smem_u32 = smem_u32_of(smem);

    float acc[2][8][4] = {};
    gemm_mainloop(ctx, smem_u32,
                  g16_buf + (size_t)rowBase * HDIM,
                  WdT16_buf + (size_t)colBase * HDIM, HDIM, tid, acc);

    const int g = ctx.lane >> 2, q = ctx.lane & 3;
    float local = 0.f;
    #pragma unroll
    for (int mf = 0; mf < 2; mf++) {
        #pragma unroll
        for (int nf = 0; nf < 8; nf++) {
            int lcol = ctx.wn * 64 + nf * 8 + q * 2;
            int col  = colBase + lcol;
            float b0 = bias_s[lcol], b1 = bias_s[lcol + 1];
            int row0 = rowBase + ctx.wm * 32 + mf * 16 + g;
            float2 x0 = __bfloat1622float2(
                *(const __nv_bfloat162*)(X16_buf + (size_t)row0 * FDIM + col));
            float2 x1 = __bfloat1622float2(
                *(const __nv_bfloat162*)(X16_buf + (size_t)(row0 + 8) * FDIM + col));
            float d0 = acc[mf][nf][0] + b0 - x0.x;
            float d1 = acc[mf][nf][1] + b1 - x0.y;
            float d2 = acc[mf][nf][2] + b0 - x1.x;
            float d3 = acc[mf][nf][3] + b1 - x1.y;
            local = fmaf(d0, d0, local);
            local = fmaf(d1, d1, local);
            local = fmaf(d2, d2, local);
            local = fmaf(d3, d3, local);
        }
    }

    red[tid] = local;
    __syncthreads();
    #pragma unroll
    for (int st = 128; st > 0; st >>= 1) {
        if (tid < st) red[tid] += red[tid + st];
        __syncthreads();
    }
    if (tid == 0) mse_partials[blockIdx.y * 8 + blockIdx.x] = red[0];
}

// ============================================================================
// wdist: compact (in registers) + bitonic sort of the SMALLER set + prefix
// sums + per-element closed form. 1 block, 1024 threads. Deterministic.
//   total = sum_{v in LARGE} [ v*(2L - ns) + S_tot - 2*PS[L] ],
//   L = #{sorted_small <= v}
// ============================================================================
__global__ void __launch_bounds__(1024) wdist_kernel(
    const int* __restrict__ s, const int* __restrict__ p_ptr)
{
    extern __shared__ __align__(16) char wsm[];
    float* buf = (float*)wsm;                    // [8192]
    float* PS  = (float*)(wsm + 32768);          // [8193]
    __shared__ int   warpBase[32];
    __shared__ float chunkScan[1024];
    __shared__ double wred[32];
    __shared__ int   s_np;
    __shared__ float s_tot;

    const int tid  = threadIdx.x;
    const int lane = tid & 31, wid = tid >> 5;
    const int p = *p_ptr;
    const int base = tid * 16;

    // ---- load 16 labels + scores; build membership mask ----
    float cv[16];
    uint32_t mask = 0;                            // bit i: s==p (protected)
    #pragma unroll
    for (int q = 0; q < 4; q++) {
        int4 v = ((const int4*)(s + base))[q];
        if (v.x == p) mask |= 1u << (q*4+0);
        if (v.y == p) mask |= 1u << (q*4+1);
        if (v.z == p) mask |= 1u << (q*4+2);
        if (v.w == p) mask |= 1u << (q*4+3);
    }
    #pragma unroll
    for (int q = 0; q < 4; q++) {
        float4 v = ((const float4*)(c_buf + base))[q];
        cv[q*4+0] = v.x; cv[q*4+1] = v.y; cv[q*4+2] = v.z; cv[q*4+3] = v.w;
    }
    int cp = __popc(mask);

    // ---- block scan of protected counts ----
    int incl = cp;
    #pragma unroll
    for (int off = 1; off < 32; off <<= 1) {
        int n = __shfl_up_sync(0xFFFFFFFFu, incl, off);
        if (lane >= off) incl += n;
    }
    if (lane == 31) warpBase[wid] = incl;
    __syncthreads();
    if (wid == 0) {
        int v = warpBase[lane];
        int vi = v;
        #pragma unroll
        for (int off = 1; off < 32; off <<= 1) {
            int n = __shfl_up_sync(0xFFFFFFFFu, vi, off);
            if (lane >= off) vi += n;
        }
        warpBase[lane] = vi - v;
        if (lane == 31) s_np = vi;
    }
    __syncthreads();
    const int np = s_np;
    const int nr = NROWS - np;
    const int exclP = warpBase[wid] + incl - cp;  // protected before my chunk

    // Sort the smaller set; iterate the larger.
    const bool sortP = (np <= nr);
    const int  ns = sortP ? np : nr;              // <= 8192
    int P2 = 1; while (P2 < ns) P2 <<= 1;         // pow2, <= 8192

    // ---- scatter small-set values into buf ----
    int o = sortP ? exclP : (base - exclP);
    #pragma unroll
    for (int i = 0; i < 16; i++) {
        bool isP = (mask >> i) & 1u;
        if (isP == sortP) buf[o++] = cv[i];
    }
    for (int i = tid; i < P2; i += 1024)
        if (i >= ns) buf[i] = __int_as_float(0x7f800000);   // +inf padding
    __syncthreads();

    // ---- bitonic sort (ascending) over P2 elements ----
    for (int k = 2; k <= P2; k <<= 1) {
        for (int j = k >> 1; j > 0; j >>= 1) {
            for (int i = tid; i < P2; i += 1024) {
                int ixj = i ^ j;
                if (ixj > i) {
                    float a = buf[i], b = buf[ixj];
                    bool up = ((i & k) == 0);
                    if ((a > b) == up) { buf[i] = b; buf[ixj] = a; }
                }
            }
            __syncthreads();
        }
    }

    // ---- exclusive prefix sums PS[0..P2] (padding counts as 0) ----
    const int chunk = (P2 + 1023) >> 10;          // elems per thread
    const int t0 = tid * chunk;
    float csum = 0.f;
    for (int t = t0; t < t0 + chunk && t < P2; t++)
        csum += (t < ns) ? buf[t] : 0.f;
    chunkScan[tid] = csum;
    __syncthreads();
    for (int off = 1; off < 1024; off <<= 1) {
        float v = (tid >= off) ? chunkScan[tid - off] : 0.f;
        __syncthreads();
        chunkScan[tid] += v;
        __syncthreads();
    }
    if (tid == 1023) s_tot = chunkScan[1023];
    {
        float run = chunkScan[tid] - csum;        // exclusive chunk base
        for (int t = t0; t < t0 + chunk && t < P2; t++) {
            PS[t] = run;
            run += (t < ns) ? buf[t] : 0.f;
        }
    }
    if (tid == 0) PS[P2] = 0.f;                   // overwritten below
    __syncthreads();
    if (tid == 0) PS[P2] = s_tot;
    __syncthreads();

    const double S_tot_d = (double)s_tot;

    // ---- per-large-element closed form, double accumulation ----
    double acc = 0.0;
    #pragma unroll
    for (int i = 0; i < 16; i++) {
        bool isP = (mask >> i) & 1u;
        if (isP != sortP) {
            float v = cv[i];
            int L = 0;
            for (int step = P2 >> 1; step > 0; step >>= 1)
                if (buf[L + step - 1] <= v) L += step;
            acc += (double)v * (double)(2 * L - ns)
                 + S_tot_d - 2.0 * (double)PS[L];
        }
    }
    #pragma unroll
    for (int off = 16; off > 0; off >>= 1)
        acc += __shfl_xor_sync(0xFFFFFFFFu, acc, off);
    if (lane == 0) wred[wid] = acc;
    __syncthreads();
    if (tid == 0) {
        double total = 0.0;
        for (int w = 0; w < 32; w++) total += wred[w];
        pair_sum_g = total;
        np_g = np;
    }
}

// ============================================================================
// Finalize (1 block): reduce mse partials, write 4 outputs.
// ============================================================================
__global__ void __launch_bounds__(256) finalize_kernel(float* __restrict__ out)
{
    __shared__ double redd[256];
    const int tid = threadIdx.x;

    double m = 0.0;
    for (int i = tid; i < 1024; i += 256) m += (double)mse_partials[i];
    redd[tid] = m;
    __syncthreads();
    for (int st = 128; st > 0; st >>= 1) {
        if (tid < st) redd[tid] += redd[tid + st];
        __syncthreads();
    }
    if (tid == 0) {
        int count = np_g;
        out[0] = (float)(redd[0] / ((double)NROWS * (double)FDIM));
        out[1] = (float)NROWS;
        out[2] = (float)(pair_sum_g / (double)count);
        out[3] = (float)count;
    }
}

// ============================================================================
extern "C" void kernel_launch(void* const* d_in, const int* in_sizes, int n_in,
                              void* d_out, int out_size)
{
    const float* X  = (const float*)d_in[0];
    const float* We = (const float*)d_in[1];
    const float* be = (const float*)d_in[2];
    const float* Wd = (const float*)d_in[3];
    const float* bd = (const float*)d_in[4];
    const float* Wc = (const float*)d_in[5];
    // d_in[6] = bc: unused — constant shift cancels in |c_i - c_j|
    const int*   s  = (const int*)d_in[7];
    const int*   p  = (const int*)d_in[8];
    float* out = (float*)d_out;

    static bool init_done = false;
    if (!init_done) {
        cudaFuncSetAttribute(gemm1_mma_kernel,
            cudaFuncAttributeMaxDynamicSharedMemorySize, SM_DYN);
        cudaFuncSetAttribute(gemm2_mma_kernel,
            cudaFuncAttributeMaxDynamicSharedMemorySize, SM_DYN);
        cudaFuncSetAttribute(wdist_kernel,
            cudaFuncAttributeMaxDynamicSharedMemorySize, WD_SMEM);
        init_done = true;
    }

    conv_all_kernel<<<XBLOCKS + 2048, 256>>>(X, We, Wd);
    gemm1_mma_kernel<<<dim3(2, NROWS / 128), 256, SM_DYN>>>(be, Wc);
    wdist_kernel<<<1, 1024, WD_SMEM>>>(s, p);
    gemm2_mma_kernel<<<dim3(8, NROWS / 128), 256, SM_DYN>>>(bd);
    finalize_kernel<<<1, 256>>>(out);
}

// round 16
// speedup vs baseline: 1.9029x; 1.9029x over previous
#include <cuda_runtime.h>
#include <cuda_bf16.h>
#include <cstdint>

// Problem dims (fixed by the dataset)
#define NROWS 16384
#define FDIM  1024
#define HDIM  256

#define SMEM_SWIZZLE(off) ((off) ^ (((off) >> 3) & 0x70))

// ============================================================================
// Device scratch (static allocation is the allowed path)
// ============================================================================
__device__ __nv_bfloat16 X16_buf[NROWS * FDIM];    // 32 MB
__device__ __nv_bfloat16 WeT16_buf[HDIM * FDIM];   // [256][1024]: WeT[n][k] = We[k][n]
__device__ __nv_bfloat16 WdT16_buf[FDIM * HDIM];   // [1024][256]: WdT[n][k] = Wd[k][n]
__device__ __nv_bfloat16 g16_buf[NROWS * HDIM];    // 8 MB
__device__ float c_buf[NROWS];                     // critic scores (bc dropped: cancels)
__device__ float c_prot[NROWS];
__device__ float c_rest[NROWS];
__device__ int   np_g, nr_g;
__device__ float mse_partials[1024];
__device__ float pair_partials[1024];

// ============================================================================
// mma.sync / cp.async helpers (legal on base sm_103 target)
// ============================================================================
__device__ __forceinline__ void ldmatrix_x4(uint32_t& r0, uint32_t& r1,
                                            uint32_t& r2, uint32_t& r3,
                                            uint32_t smem_addr) {
    asm volatile("ldmatrix.sync.aligned.m8n8.x4.shared.b16 {%0,%1,%2,%3}, [%4];"
                 : "=r"(r0), "=r"(r1), "=r"(r2), "=r"(r3) : "r"(smem_addr));
}
__device__ __forceinline__ void mma_16816(float& c0, float& c1, float& c2, float& c3,
                                          uint32_t a0, uint32_t a1, uint32_t a2, uint32_t a3,
                                          uint32_t b0, uint32_t b1) {
    asm volatile("mma.sync.aligned.m16n8k16.row.col.f32.bf16.bf16.f32 "
                 "{%0,%1,%2,%3}, {%4,%5,%6,%7}, {%8,%9}, {%0,%1,%2,%3};"
                 : "+f"(c0), "+f"(c1), "+f"(c2), "+f"(c3)
                 : "r"(a0), "r"(a1), "r"(a2), "r"(a3), "r"(b0), "r"(b1));
}
__device__ __forceinline__ uint32_t smem_u32_of(const void* p) {
    uint32_t a;
    asm("{ .reg .u64 t; cvta.to.shared.u64 t, %1; cvt.u32.u64 %0, t; }" : "=r"(a) : "l"(p));
    return a;
}
__device__ __forceinline__ void cp_async16(uint32_t dst_smem, const void* src) {
    asm volatile("cp.async.cg.shared.global [%0], [%1], 16;"
                 :: "r"(dst_smem), "l"(src));
}
#define CP_COMMIT()  asm volatile("cp.async.commit_group;" ::: "memory")
#define CP_WAIT_0()  asm volatile("cp.async.wait_group 0;" ::: "memory")

// ============================================================================
// Combined conversion kernel:
//   blocks [0, 16384): X fp32 -> bf16 (one float4 per thread)
//   blocks [16384, 18432): WeT/WdT transpose+convert, c_buf zero
// ============================================================================
#define XBLOCKS (NROWS * FDIM / 4 / 256)          // 16384
__global__ void __launch_bounds__(256) conv_all_kernel(
    const float* __restrict__ X, const float* __restrict__ We,
    const float* __restrict__ Wd)
{
    if (blockIdx.x < XBLOCKS) {
        int idx = blockIdx.x * 256 + threadIdx.x;
        float4 v = ((const float4*)X)[idx];
        __nv_bfloat162 h0 = __floats2bfloat162_rn(v.x, v.y);
        __nv_bfloat162 h1 = __floats2bfloat162_rn(v.z, v.w);
        uint2 o;
        o.x = *reinterpret_cast<uint32_t*>(&h0);
        o.y = *reinterpret_cast<uint32_t*>(&h1);
        ((uint2*)X16_buf)[idx] = o;
    } else {
        int idx = (blockIdx.x - XBLOCKS) * 256 + threadIdx.x;   // [0, 524288)
        if (idx < NROWS) c_buf[idx] = 0.f;
        if (idx < HDIM * FDIM) {
            int n = idx >> 10, k = idx & 1023;
            WeT16_buf[idx] = __float2bfloat16_rn(We[(size_t)k * HDIM + n]);
        } else {
            int j = idx - HDIM * FDIM;
            int n = j >> 8, k = j & 255;
            WdT16_buf[j] = __float2bfloat16_rn(Wd[(size_t)k * FDIM + n]);
        }
    }
}

// ============================================================================
// Warp-tile MMA over one staged (A,B) 128x64 slab pair.
// 8 warps as 4(M) x 2(N); warp tile 32x64. acc[mf(2)][nf(8)][4].
// ============================================================================
struct MmaCtx { int wm, wn, lane; };

__device__ __forceinline__ void mma_block_iter(
    const MmaCtx& ctx, uint32_t sA, uint32_t sB, float acc[2][8][4])
{
    const int lrow  = ctx.lane & 15;          // ldmatrix row-within-16
    const int lcolb = (ctx.lane >> 4) * 16;   // +16B for k8..15 half
    #pragma unroll
    for (int ks = 0; ks < 4; ks++) {
        const int kb = ks * 32;               // byte col offset of this k16
        uint32_t a[2][4], b[4][4];
        #pragma unroll
        for (int mf = 0; mf < 2; mf++) {
            int off = (ctx.wm * 32 + mf * 16 + lrow) * 128 + kb + lcolb;
            ldmatrix_x4(a[mf][0], a[mf][1], a[mf][2], a[mf][3],
                        sA + SMEM_SWIZZLE(off));
        }
        #pragma unroll
        for (int nf = 0; nf < 4; nf++) {
            int off = (ctx.wn * 64 + nf * 16 + lrow) * 128 + kb + lcolb;
            ldmatrix_x4(b[nf][0], b[nf][1], b[nf][2], b[nf][3],
                        sB + SMEM_SWIZZLE(off));
        }
        #pragma unroll
        for (int mf = 0; mf < 2; mf++)
            #pragma unroll
            for (int nf = 0; nf < 4; nf++) {
                mma_16816(acc[mf][2*nf][0], acc[mf][2*nf][1],
                          acc[mf][2*nf][2], acc[mf][2*nf][3],
                          a[mf][0], a[mf][1], a[mf][2], a[mf][3],
                          b[nf][0], b[nf][2]);
                mma_16816(acc[mf][2*nf+1][0], acc[mf][2*nf+1][1],
                          acc[mf][2*nf+1][2], acc[mf][2*nf+1][3],
                          a[mf][0], a[mf][1], a[mf][2], a[mf][3],
                          b[nf][1], b[nf][3]);
            }
    }
}

// Issue cp.async for one 128x64 bf16 tile (row stride K_TOT elems).
__device__ __forceinline__ void stage_tile_async(
    uint32_t dst_u32, const __nv_bfloat16* __restrict__ src,
    int K_TOT, int k0, int tid)
{
    #pragma unroll
    for (int it = 0; it < 4; it++) {
        int idx = tid + it * 256;
        int row = idx >> 3, k8 = idx & 7;
        const void* gp = (const char*)src + ((size_t)row * K_TOT + k0) * 2 + k8 * 16;
        cp_async16(dst_u32 + SMEM_SWIZZLE(row * 128 + k8 * 16), gp);
    }
}

// 2-stage pipelined mainloop, ONE __syncthreads per slab (best measured).
__device__ __forceinline__ void gemm_mainloop(
    const MmaCtx& ctx, uint32_t smem_u32,
    const __nv_bfloat16* __restrict__ Ag, const __nv_bfloat16* __restrict__ Bg,
    int K_TOT, int tid, float acc[2][8][4])
{
    const int NS = K_TOT >> 6;
    stage_tile_async(smem_u32,         Ag, K_TOT, 0, tid);
    stage_tile_async(smem_u32 + 16384, Bg, K_TOT, 0, tid);
    CP_COMMIT();
    for (int s = 0; s < NS; s++) {
        CP_WAIT_0();
        __syncthreads();
        if (s + 1 < NS) {
            const uint32_t nxt = smem_u32 + ((s + 1) & 1) * 32768;
            stage_tile_async(nxt,         Ag, K_TOT, (s + 1) << 6, tid);
            stage_tile_async(nxt + 16384, Bg, K_TOT, (s + 1) << 6, tid);
            CP_COMMIT();
        }
        const uint32_t cur = smem_u32 + (s & 1) * 32768;
        mma_block_iter(ctx, cur, cur + 16384, acc);
    }
}

// ============================================================================
// GEMM1 + fused critic: g16 = bf16(X16 @ WeT^T + be); c += partial(g @ Wc).
// grid = (2, 128), 256 threads.
// ============================================================================
__global__ void __launch_bounds__(256) gemm1_mma_kernel(
    const float* __restrict__ be, const float* __restrict__ Wc)
{
    extern __shared__ __align__(1024) char smem[];   // 65536 B: 2 stages x (A|B)
    __shared__ float bias_s[128], Wc_s[128];
    __shared__ float csm[2][128];

    const int tid = threadIdx.x;
    const int warp = tid >> 5;
    const int rowBase = blockIdx.y * 128;
    const int colBase = blockIdx.x * 128;
    if (tid < 128) { bias_s[tid] = be[colBase + tid]; Wc_s[tid] = Wc[colBase + tid]; }

    MmaCtx ctx; ctx.wm = warp & 3; ctx.wn = warp >> 2; ctx.lane = tid & 31;
    uint32_t smem_u32 = smem_u32_of(smem);

    float acc[2][8][4] = {};
    gemm_mainloop(ctx, smem_u32,
                  X16_buf + (size_t)rowBase * FDIM,
                  WeT16_buf + (size_t)colBase * FDIM, FDIM, tid, acc);

    // Epilogue: + bias, store bf16 g; accumulate critic partial dot
    const int g = ctx.lane >> 2, q = ctx.lane & 3;
    float sdot[2][2] = {};
    #pragma unroll
    for (int mf = 0; mf < 2; mf++) {
        #pragma unroll
        for (int nf = 0; nf < 8; nf++) {
            int lcol = ctx.wn * 64 + nf * 8 + q * 2;
            int col  = colBase + lcol;
            float b0 = bias_s[lcol], b1 = bias_s[lcol + 1];
            float w0 = Wc_s[lcol],   w1 = Wc_s[lcol + 1];
            float a0 = acc[mf][nf][0] + b0, a1 = acc[mf][nf][1] + b1;
            float a2 = acc[mf][nf][2] + b0, a3 = acc[mf][nf][3] + b1;
            int row0 = rowBase + ctx.wm * 32 + mf * 16 + g;
            __nv_bfloat162 h0 = __floats2bfloat162_rn(a0, a1);
            __nv_bfloat162 h1 = __floats2bfloat162_rn(a2, a3);
            *(__nv_bfloat162*)(g16_buf + (size_t)row0 * HDIM + col) = h0;
            *(__nv_bfloat162*)(g16_buf + (size_t)(row0 + 8) * HDIM + col) = h1;
            sdot[mf][0] = fmaf(a0, w0, fmaf(a1, w1, sdot[mf][0]));
            sdot[mf][1] = fmaf(a2, w0, fmaf(a3, w1, sdot[mf][1]));
        }
    }
    #pragma unroll
    for (int off = 1; off <= 2; off <<= 1) {
        #pragma unroll
        for (int mf = 0; mf < 2; mf++) {
            sdot[mf][0] += __shfl_xor_sync(0xFFFFFFFFu, sdot[mf][0], off);
            sdot[mf][1] += __shfl_xor_sync(0xFFFFFFFFu, sdot[mf][1], off);
        }
    }
    if (q == 0) {
        #pragma unroll
        for (int mf = 0; mf < 2; mf++) {
            int lr = ctx.wm * 32 + mf * 16 + g;
            csm[ctx.wn][lr]     = sdot[mf][0];
            csm[ctx.wn][lr + 8] = sdot[mf][1];
        }
    }
    __syncthreads();
    if (tid < 128)
        atomicAdd(&c_buf[rowBase + tid], csm[0][tid] + csm[1][tid]);
}

// ============================================================================
// GEMM2 fused MSE: rec = g16 @ WdT^T + bd; accum (rec - X16)^2.
// grid = (8, 128), 256 threads.
// ============================================================================
__global__ void __launch_bounds__(256) gemm2_mma_kernel(const float* __restrict__ bd)
{
    extern __shared__ __align__(1024) char smem[];
    __shared__ float bias_s[128];
    __shared__ float red[256];

    const int tid = threadIdx.x;
    const int warp = tid >> 5;
    const int rowBase = blockIdx.y * 128;
    const int colBase = blockIdx.x * 128;
    if (tid < 128) bias_s[tid] = bd[colBase + tid];

    MmaCtx ctx; ctx.wm = warp & 3; ctx.wn = warp >> 2; ctx.lane = tid & 31;
    uint32_t smem_u32 = smem_u32_of(smem);

    float acc[2][8][4] = {};
    gemm_mainloop(ctx, smem_u32,
                  g16_buf + (size_t)rowBase * HDIM,
                  WdT16_buf + (size_t)colBase * HDIM, HDIM, tid, acc);

    // Fused epilogue: (acc + bd - X16)^2
    const int g = ctx.lane >> 2, q = ctx.lane & 3;
    float local = 0.f;
    #pragma unroll
    for (int mf = 0; mf < 2; mf++) {
        #pragma unroll
        for (int nf = 0; nf < 8; nf++) {
            int lcol = ctx.wn * 64 + nf * 8 + q * 2;
            int col  = colBase + lcol;
            float b0 = bias_s[lcol], b1 = bias_s[lcol + 1];
            int row0 = rowBase + ctx.wm * 32 + mf * 16 + g;
            float2 x0 = __bfloat1622float2(
                *(const __nv_bfloat162*)(X16_buf + (size_t)row0 * FDIM + col));
            float2 x1 = __bfloat1622float2(
                *(const __nv_bfloat162*)(X16_buf + (size_t)(row0 + 8) * FDIM + col));
            float d0 = acc[mf][nf][0] + b0 - x0.x;
            float d1 = acc[mf][nf][1] + b1 - x0.y;
            float d2 = acc[mf][nf][2] + b0 - x1.x;
            float d3 = acc[mf][nf][3] + b1 - x1.y;
            local = fmaf(d0, d0, local);
            local = fmaf(d1, d1, local);
            local = fmaf(d2, d2, local);
            local = fmaf(d3, d3, local);
        }
    }

    red[tid] = local;
    __syncthreads();
    #pragma unroll
    for (int st = 128; st > 0; st >>= 1) {
        if (tid < st) red[tid] += red[tid + st];
        __syncthreads();
    }
    if (tid == 0) mse_partials[blockIdx.y * 8 + blockIdx.x] = red[0];
}

// ============================================================================
// Compaction (fast): 1024 threads, 16 elems/thread, vectorized loads,
// shfl warp scan + 2-level block scan. Runs ALONE on the main stream.
// ============================================================================
__global__ void __launch_bounds__(1024) compact_kernel(
    const int* __restrict__ s, const int* __restrict__ p_ptr)
{
    __shared__ int warpBase[32];
    const int tid  = threadIdx.x;
    const int lane = tid & 31, wid = tid >> 5;
    const int p = *p_ptr;
    const int base = tid * 16;

    int sv[16];
    #pragma unroll
    for (int q = 0; q < 4; q++) {
        int4 v = ((const int4*)(s + base))[q];
        sv[q*4+0] = v.x; sv[q*4+1] = v.y; sv[q*4+2] = v.z; sv[q*4+3] = v.w;
    }
    int cp = 0;
    #pragma unroll
    for (int i = 0; i < 16; i++) cp += (sv[i] == p) ? 1 : 0;

    int incl = cp;
    #pragma unroll
    for (int off = 1; off < 32; off <<= 1) {
        int n = __shfl_up_sync(0xFFFFFFFFu, incl, off);
        if (lane >= off) incl += n;
    }
    if (lane == 31) warpBase[wid] = incl;
    __syncthreads();
    if (wid == 0) {
        int v = warpBase[lane];
        int vi = v;
        #pragma unroll
        for (int off = 1; off < 32; off <<= 1) {
            int n = __shfl_up_sync(0xFFFFFFFFu, vi, off);
            if (lane >= off) vi += n;
        }
        warpBase[lane] = vi - v;
        if (lane == 31) { np_g = vi; nr_g = NROWS - vi; }
    }
    __syncthreads();

    int oP = warpBase[wid] + incl - cp;
    int oR = base - oP;

    float cv[16];
    #pragma unroll
    for (int q = 0; q < 4; q++) {
        float4 v = ((const float4*)(c_buf + base))[q];
        cv[q*4+0] = v.x; cv[q*4+1] = v.y; cv[q*4+2] = v.z; cv[q*4+3] = v.w;
    }
    #pragma unroll
    for (int i = 0; i < 16; i++) {
        if (sv[i] == p) c_prot[oP++] = cv[i];
        else            c_rest[oR++] = cv[i];
    }
}

// ============================================================================
// Pairwise L1 over compacted arrays. grid (16,64): 1024 blocks for SM balance
// (measured: co-run occ 67%, issue 80%). j-chunk 256, 4 i per thread.
// ============================================================================
__global__ void __launch_bounds__(256) pairwise_kernel()
{
    __shared__ float smj[256];
    __shared__ float red[256];
    const int tid = threadIdx.x;
    const int np = np_g, nr = nr_g;
    const int iBase = blockIdx.x * 1024;
    const int jBase = blockIdx.y * 256;

    float ci0 = 0.f, ci1 = 0.f, ci2 = 0.f, ci3 = 0.f;
    int i0 = iBase + tid, i1 = i0 + 256, i2 = i0 + 512, i3 = i0 + 768;
    bool v0 = i0 < np, v1 = i1 < np, v2 = i2 < np, v3 = i3 < np;
    if (v0) ci0 = c_prot[i0];
    if (v1) ci1 = c_prot[i1];
    if (v2) ci2 = c_prot[i2];
    if (v3) ci3 = c_prot[i3];

    smj[tid] = (jBase + tid < nr) ? c_rest[jBase + tid] : 0.f;
    __syncthreads();

    int jn = nr - jBase;
    if (jn > 256) jn = 256;
    if (jn < 0) jn = 0;
    float a0 = 0.f, a1 = 0.f, a2 = 0.f, a3 = 0.f;
    for (int j = 0; j < jn; j++) {
        float cj = smj[j];
        a0 += fabsf(ci0 - cj);
        a1 += fabsf(ci1 - cj);
        a2 += fabsf(ci2 - cj);
        a3 += fabsf(ci3 - cj);
    }
    float local = (v0 ? a0 : 0.f) + (v1 ? a1 : 0.f) + (v2 ? a2 : 0.f) + (v3 ? a3 : 0.f);

    red[tid] = local;
    __syncthreads();
    #pragma unroll
    for (int st = 128; st > 0; st >>= 1) {
        if (tid < st) red[tid] += red[tid + st];
        __syncthreads();
    }
    if (tid == 0) pair_partials[blockIdx.y * 16 + blockIdx.x] = red[0];
}

// ============================================================================
// Finalize (1 block): reduce partials, write 4 outputs.
// ============================================================================
__global__ void __launch_bounds__(256) finalize_kernel(float* __restrict__ out)
{
    __shared__ double redd[256];
    const int tid = threadIdx.x;

    double m = 0.0;
    for (int i = tid; i < 1024; i += 256) m += (double)mse_partials[i];
    redd[tid] = m;
    __syncthreads();
    for (int st = 128; st > 0; st >>= 1) {
        if (tid < st) redd[tid] += redd[tid + st];
        __syncthreads();
    }
    double mse_sum = redd[0];
    __syncthreads();

    double pr = 0.0;
    for (int i = tid; i < 1024; i += 256) pr += (double)pair_partials[i];
    redd[tid] = pr;
    __syncthreads();
    for (int st = 128; st > 0; st >>= 1) {
        if (tid < st) redd[tid] += redd[tid + st];
        __syncthreads();
    }
    double pair_sum = redd[0];

    if (tid == 0) {
        int count = np_g;
        out[0] = (float)(mse_sum / ((double)NROWS * (double)FDIM));
        out[1] = (float)NROWS;
        out[2] = (float)(pair_sum / (double)count);
        out[3] = (float)count;
    }
}

// ============================================================================
extern "C" void kernel_launch(void* const* d_in, const int* in_sizes, int n_in,
                              void* d_out, int out_size)
{
    const float* X  = (const float*)d_in[0];
    const float* We = (const float*)d_in[1];
    const float* be = (const float*)d_in[2];
    const float* Wd = (const float*)d_in[3];
    const float* bd = (const float*)d_in[4];
    const float* Wc = (const float*)d_in[5];
    // d_in[6] = bc: unused — constant shift cancels in |c_i - c_j|
    const int*   s  = (const int*)d_in[7];
    const int*   p  = (const int*)d_in[8];
    float* out = (float*)d_out;

    // One-time host-object setup (no device memory; identical GPU work per call)
    static cudaStream_t s2 = nullptr;
    static cudaEvent_t evA = nullptr, evB = nullptr;
    if (!s2) {
        cudaStreamCreateWithFlags(&s2, cudaStreamNonBlocking);
        cudaEventCreateWithFlags(&evA, cudaEventDisableTiming);
        cudaEventCreateWithFlags(&evB, cudaEventDisableTiming);
        cudaFuncSetAttribute(gemm1_mma_kernel,
            cudaFuncAttributeMaxDynamicSharedMemorySize, 65536);
        cudaFuncSetAttribute(gemm2_mma_kernel,
            cudaFuncAttributeMaxDynamicSharedMemorySize, 65536);
    }

    // All conversions in one launch
    conv_all_kernel<<<XBLOCKS + 2048, 256>>>(X, We, Wd);

    gemm1_mma_kernel<<<dim3(2, NROWS / 128), 256, 65536>>>(be, Wc);

    // Compact runs ALONE on main stream (full machine) right after gemm1
    compact_kernel<<<1, 1024>>>(s, p);

    // Fork only pairwise beside gemm2 (fma pipe vs tensor pipe overlap)
    cudaEventRecord(evA, 0);
    cudaStreamWaitEvent(s2, evA, 0);
    pairwise_kernel<<<dim3(16, 64), 256, 0, s2>>>();
    cudaEventRecord(evB, s2);

    gemm2_mma_kernel<<<dim3(8, NROWS / 128), 256, 65536>>>(bd);

    cudaStreamWaitEvent(0, evB, 0);
    finalize_kernel<<<1, 256>>>(out);
}